// round 17
// baseline (speedup 1.0000x reference)
#include <cuda_runtime.h>
#include <cuda_fp16.h>
#include <cstdint>

#define N_NODES 1000
#define HIDDEN  256
#define IN_DIM  128
#define N_EDGES 64000
#define N_TILES 1000   // 500 edge-blocks x 2 col-halves

// Scratch (device globals: no allocation allowed)
__device__ float g_C[N_NODES * HIDDEN];    // A - B + b1   (per node)
__device__ float g_B[N_NODES * HIDDEN];    // B = X @ W1b^T (per node)
__device__ float g_H0[N_NODES * HIDDEN];   // ping-pong node features
__device__ float g_H1[N_NODES * HIDDEN];
__device__ __half g_Wh[5 * HIDDEN * HIDDEN];  // W2 hi fp16, all 5 layers
__device__ __half g_Wl[5 * HIDDEN * HIDDEN];  // W2 lo fp16 residual
__device__ int   g_src[N_EDGES];
__device__ int   g_dst[N_EDGES];
__device__ int   g_ctr[5];                 // per-layer persistent tile counters

// ---------------------------------------------------------------------------
__device__ __forceinline__ uint32_t smem_u32(const void* p) {
    uint32_t a;
    asm("{ .reg .u64 t; cvta.to.shared.u64 t, %1; cvt.u32.u64 %0, t; }"
        : "=r"(a) : "l"(p));
    return a;
}
__device__ __forceinline__ void ldmatrix_x4(uint32_t* r, uint32_t addr) {
    asm volatile(
        "ldmatrix.sync.aligned.m8n8.x4.shared.b16 {%0, %1, %2, %3}, [%4];"
        : "=r"(r[0]), "=r"(r[1]), "=r"(r[2]), "=r"(r[3]) : "r"(addr));
}
// fp16 inputs, fp32 accumulate
__device__ __forceinline__ void mma_f32acc(float* d, const uint32_t* a,
                                           const uint32_t* b) {
    asm volatile(
        "mma.sync.aligned.m16n8k16.row.col.f32.f16.f16.f32 "
        "{%0, %1, %2, %3}, {%4, %5, %6, %7}, {%8, %9}, {%0, %1, %2, %3};"
        : "+f"(d[0]), "+f"(d[1]), "+f"(d[2]), "+f"(d[3])
        : "r"(a[0]), "r"(a[1]), "r"(a[2]), "r"(a[3]), "r"(b[0]), "r"(b[1]));
}
__device__ __forceinline__ void cp_async16(uint32_t saddr, const void* gaddr) {
    asm volatile("cp.async.ca.shared.global [%0], [%1], 16;"
                 :: "r"(saddr), "l"(gaddr));
}
__device__ __forceinline__ void cp_commit() {
    asm volatile("cp.async.commit_group;");
}
__device__ __forceinline__ void cp_wait0() {
    asm volatile("cp.async.wait_group 0;");
}

// ---------------------------------------------------------------------------
// Self-detecting edge-index conversion (int64 vs int32), clamped.
__global__ void convert_idx_auto(const int* __restrict__ raw) {
    const unsigned int* w = (const unsigned int*)raw;
    unsigned int acc = 0;
#pragma unroll
    for (int i = 0; i < 16; i++) acc |= w[2 * i + 1];
    const bool is64 = (acc == 0u);

    int e = blockIdx.x * blockDim.x + threadIdx.x;
    if (e >= N_EDGES) return;
    int s, d;
    if (is64) { s = raw[2 * e]; d = raw[2 * (N_EDGES + e)]; }
    else      { s = raw[e];     d = raw[N_EDGES + e]; }
    g_src[e] = min(max(s, 0), N_NODES - 1);
    g_dst[e] = min(max(d, 0), N_NODES - 1);
}

// ---------------------------------------------------------------------------
// One-time: split all 5 W2 into fp16 hi/lo; zero g_H0 (layer-0 output);
// zero the 5 persistent tile counters (re-runs every graph replay).
__global__ void prep_w_all(const float* __restrict__ w0, const float* __restrict__ w1,
                           const float* __restrict__ w2, const float* __restrict__ w3,
                           const float* __restrict__ w4) {
    const float* ws[5] = {w0, w1, w2, w3, w4};
    int b = blockIdx.x;           // 0..1279
    int l = b >> 8;
    int i = (b & 255) * 256 + threadIdx.x;
    float w = ws[l][i];
    __half hi = __float2half_rn(w);
    __half lo = __float2half_rn(w - __half2float(hi));
    g_Wh[l * (HIDDEN * HIDDEN) + i] = hi;
    g_Wl[l * (HIDDEN * HIDDEN) + i] = lo;
    if (b < 250) {  // 250*256 = 64000 float4 = full g_H0
        ((float4*)g_H0)[b * 256 + threadIdx.x] =
            make_float4(0.f, 0.f, 0.f, 0.f);
    }
    if (b == 1279 && threadIdx.x < 5) g_ctr[threadIdx.x] = 0;
}

// ---------------------------------------------------------------------------
// Node GEMM: C = A - B + b1, B = H @ W1b^T  (fp32, tiny: 1000x256)
// in_sel: 0 -> x, 1 -> g_H0, 2 -> g_H1
template <int DIN>
__global__ __launch_bounds__(256) void node_gemm(
    const float* __restrict__ x, const float* __restrict__ W1,
    const float* __restrict__ b1, int in_sel)
{
    const float* H = (in_sel == 0) ? x : (in_sel == 1 ? g_H0 : g_H1);
    __shared__ float Hs[16][DIN];
    const int tid = threadIdx.x;
    const int n_base = blockIdx.x * 16;

    const int nvec = 16 * DIN / 4;
    for (int i = tid; i < nvec; i += 256) {
        int row = i / (DIN / 4);
        int c4 = i % (DIN / 4);
        int n = n_base + row;
        float4 v = make_float4(0.f, 0.f, 0.f, 0.f);
        if (n < N_NODES) v = ((const float4*)(H + (size_t)n * DIN))[c4];
        ((float4*)&Hs[row][0])[c4] = v;
    }
    __syncthreads();

    const int o = blockIdx.y * 128 + (tid & 127);
    const int ng = tid >> 7;

    float accA[8], accB[8];
#pragma unroll
    for (int j = 0; j < 8; j++) { accA[j] = 0.f; accB[j] = 0.f; }

    const float4* wA4 = (const float4*)(W1 + (size_t)o * 2 * DIN);
    const float4* wB4 = (const float4*)(W1 + (size_t)o * 2 * DIN + DIN);

    for (int k4 = 0; k4 < DIN / 4; k4++) {
        float4 wa = wA4[k4];
        float4 wb = wB4[k4];
        int kk = k4 * 4;
#pragma unroll
        for (int j = 0; j < 8; j++) {
            float h0 = Hs[ng * 8 + j][kk + 0];
            float h1 = Hs[ng * 8 + j][kk + 1];
            float h2 = Hs[ng * 8 + j][kk + 2];
            float h3 = Hs[ng * 8 + j][kk + 3];
            accA[j] += h0 * wa.x + h1 * wa.y + h2 * wa.z + h3 * wa.w;
            accB[j] += h0 * wb.x + h1 * wb.y + h2 * wb.z + h3 * wb.w;
        }
    }

    float bb = b1[o];
#pragma unroll
    for (int j = 0; j < 8; j++) {
        int n = n_base + ng * 8 + j;
        if (n < N_NODES) {
            g_B[n * HIDDEN + o] = accB[j];
            g_C[n * HIDDEN + o] = accA[j] - accB[j] + bb;
        }
    }
}

// ---------------------------------------------------------------------------
// Persistent HMMA fused edge kernel (2-pass W-split fp16, validated R16
// inner loop byte-for-byte): 304 persistent CTAs pull tiles from a dynamic
// per-layer counter -> no wave-quantization tail. 256 thr, 2 CTAs/SM,
// tile = 128 edges x 128 cols, warp tile 32x64, K=256 dbl-buffered chunks.
// Also zeros the NEXT layer's output buffer per tile (race-free as in R15).
// out_sel/zero_sel: 0 none, 1 g_H0, 2 g_H1, 3 dout.

#define TM 128
#define TN 128
#define TK 32
#define SK 40   // padded fp16 k-stride

#define A_STAGE (TM * SK * 2)              // 10240
#define B_STAGE (TN * SK * 2)              // 10240
#define OFF_A   0                          // 2 bufs: 20480
#define OFF_BH  (2 * A_STAGE)              // 20480 (2 bufs)
#define OFF_BL  (2 * A_STAGE + 2 * B_STAGE)// 40960 (2 bufs)
#define OFF_DST (2 * A_STAGE + 4 * B_STAGE)// 61440
#define OFF_SRC (OFF_DST + 512)
#define OFF_B2  (OFF_SRC + 512)
#define OFF_T   (OFF_B2 + 512)
#define SM_TOTAL (OFF_T + 16)              // 62992

__global__ __launch_bounds__(256, 2) void edge_hmma_kernel(
    const float* __restrict__ b2, float* __restrict__ dout,
    int out_sel, int zero_sel, int loff, int lidx)
{
    extern __shared__ char smem[];
    float* out = (out_sel == 3) ? dout : (out_sel == 1 ? g_H0 : g_H1);
    const uint32_t sb = smem_u32(smem);
    const int tid = threadIdx.x;
    const int wid = tid >> 5;
    const int lane = tid & 31;

    int* dstS = (int*)(smem + OFF_DST);
    int* srcS = (int*)(smem + OFF_SRC);
    float* b2s = (float*)(smem + OFF_B2);
    int* tS = (int*)(smem + OFF_T);

    const int wm = (wid >> 1) * 32;  // warp M offset (0..96)
    const int wn = (wid & 1) * 64;   // warp N offset (0 or 64)

    const int a_row = lane & 15;
    const int a_kof = (lane >> 4) << 3;
    const int b_row = ((lane >> 4) << 3) + (lane & 7);
    const int b_kof = ((lane >> 3) & 1) << 3;

    const __half* Whp = g_Wh + loff;
    const __half* Wlp = g_Wl + loff;

    while (true) {
        if (tid == 0) tS[0] = atomicAdd(&g_ctr[lidx], 1);
        __syncthreads();
        const int t = tS[0];
        if (t >= N_TILES) break;
        const int e0 = (t >> 1) * TM;
        const int n0 = (t & 1) * TN;

        // zero next layer's output buffer: each tile zeros its 1KB slice
        if (zero_sel != 0 && tid < 64) {
            float4* zp = (zero_sel == 3) ? (float4*)dout
                                         : (zero_sel == 1 ? (float4*)g_H0
                                                          : (float4*)g_H1);
            zp[t * 64 + tid] = make_float4(0.f, 0.f, 0.f, 0.f);
        }

        if (tid < TM) {
            srcS[tid] = g_src[e0 + tid];
            dstS[tid] = g_dst[e0 + tid];
        }
        if (tid < TN) b2s[tid] = b2[n0 + tid];
        __syncthreads();

        float acc[2][8][4];
#pragma unroll
        for (int i = 0; i < 2; i++)
#pragma unroll
            for (int j = 0; j < 8; j++)
#pragma unroll
                for (int r = 0; r < 4; r++) acc[i][j][r] = 0.f;

        auto issue_W = [&](int buf, int kt) {
#pragma unroll
            for (int i = 0; i < 4; i++) {
                int id = tid + i * 256;
                int slab = id >> 9;
                int rem = id & 511;
                int row = rem >> 2;
                int q = rem & 3;
                uint32_t so = (slab ? OFF_BL : OFF_BH) + buf * B_STAGE +
                              (uint32_t)(row * SK + q * 8) * 2;
                const __half* g = slab ? Wlp : Whp;
                cp_async16(sb + so, g + (n0 + row) * HIDDEN + kt + q * 8);
            }
            cp_commit();
        };
        auto ldg_Z = [&](int h, int kt, float4& cz, float4& bz) {
            int id = tid + h * 256;
            int row = id >> 3;
            int k4 = (id & 7) * 4;
            cz = *(const float4*)&g_C[dstS[row] * HIDDEN + kt + k4];
            bz = *(const float4*)&g_B[srcS[row] * HIDDEN + kt + k4];
        };
        auto sts_Z = [&](int h, int buf, const float4& cz, const float4& bz) {
            int id = tid + h * 256;
            int row = id >> 3;
            int k4 = (id & 7) * 4;
            __half2 h01 = __floats2half2_rn(fmaxf(cz.x + bz.x, 0.f),
                                            fmaxf(cz.y + bz.y, 0.f));
            __half2 h23 = __floats2half2_rn(fmaxf(cz.z + bz.z, 0.f),
                                            fmaxf(cz.w + bz.w, 0.f));
            uint32_t eo = (uint32_t)(row * SK + k4) * 2;
            *(uint2*)(smem + OFF_A + buf * A_STAGE + eo) =
                make_uint2(*(uint32_t*)&h01, *(uint32_t*)&h23);
        };
        auto mma_ks = [&](int buf, int ks) {
            uint32_t a[2][4];
#pragma unroll
            for (int mt = 0; mt < 2; mt++) {
                uint32_t ao = (uint32_t)((wm + mt * 16 + a_row) * SK + ks + a_kof) * 2;
                ldmatrix_x4(a[mt], sb + OFF_A + buf * A_STAGE + ao);
            }
#pragma unroll
            for (int nt = 0; nt < 4; nt++) {
                uint32_t bh[4], bl[4];
                uint32_t bo = (uint32_t)((wn + nt * 16 + b_row) * SK + ks + b_kof) * 2;
                ldmatrix_x4(bh, sb + OFF_BH + buf * B_STAGE + bo);
                ldmatrix_x4(bl, sb + OFF_BL + buf * B_STAGE + bo);
#pragma unroll
                for (int mt = 0; mt < 2; mt++) {
                    mma_f32acc(acc[mt][nt * 2 + 0], a[mt], &bh[0]);
                    mma_f32acc(acc[mt][nt * 2 + 1], a[mt], &bh[2]);
                    mma_f32acc(acc[mt][nt * 2 + 0], a[mt], &bl[0]);
                    mma_f32acc(acc[mt][nt * 2 + 1], a[mt], &bl[2]);
                }
            }
        };

        // prologue: chunk 0 into buf 0
        {
            issue_W(0, 0);
            float4 cz[4], bz[4];
#pragma unroll
            for (int h = 0; h < 4; h++) ldg_Z(h, 0, cz[h], bz[h]);
#pragma unroll
            for (int h = 0; h < 4; h++) sts_Z(h, 0, cz[h], bz[h]);
            cp_wait0();
            __syncthreads();
        }
        // main pipeline over 8 chunks
        for (int c = 0; c < 8; c++) {
            const int buf = c & 1;
            const int ktn = (c + 1) * TK;
            float4 cz0, bz0, cz1, bz1, cz2, bz2, cz3, bz3;
            if (c < 7) {
                issue_W(buf ^ 1, ktn);
                ldg_Z(0, ktn, cz0, bz0);
                ldg_Z(1, ktn, cz1, bz1);
            }
            mma_ks(buf, 0);
            if (c < 7) {
                sts_Z(0, buf ^ 1, cz0, bz0);
                sts_Z(1, buf ^ 1, cz1, bz1);
                ldg_Z(2, ktn, cz2, bz2);
                ldg_Z(3, ktn, cz3, bz3);
            }
            mma_ks(buf, 16);
            if (c < 7) {
                sts_Z(2, buf ^ 1, cz2, bz2);
                sts_Z(3, buf ^ 1, cz3, bz3);
                cp_wait0();
            }
            __syncthreads();
        }

        // epilogue: bias, clamp, int atomicMax scatter (nonneg floats)
        int* oi = (int*)out;
        const int gr = lane >> 2;
        const int gc = (lane & 3) * 2;
#pragma unroll
        for (int mt = 0; mt < 2; mt++) {
#pragma unroll
            for (int half = 0; half < 2; half++) {
                int row = wm + mt * 16 + gr + half * 8;
                int d = dstS[row];
                int base = d * HIDDEN + n0;
#pragma unroll
                for (int ns = 0; ns < 8; ns++) {
                    int col = wn + ns * 8 + gc;
                    float v0 = acc[mt][ns][half * 2 + 0] + b2s[col];
                    float v1 = acc[mt][ns][half * 2 + 1] + b2s[col + 1];
                    if (v0 > 0.f) atomicMax(&oi[base + col], __float_as_int(v0));
                    if (v1 > 0.f) atomicMax(&oi[base + col + 1], __float_as_int(v1));
                }
            }
        }
        __syncthreads();   // protect dstS/srcS before next tile's loads
    }
}

// ---------------------------------------------------------------------------
extern "C" void kernel_launch(void* const* d_in, const int* in_sizes, int n_in,
                              void* d_out, int out_size) {
    const float* x = (const float*)d_in[0];
    const int* ei_raw = (const int*)d_in[1];

    static bool attr_set = false;
    if (!attr_set) {
        cudaFuncSetAttribute(edge_hmma_kernel,
                             cudaFuncAttributeMaxDynamicSharedMemorySize,
                             SM_TOTAL);
        attr_set = true;
    }

    // launch 0: index conversion
    convert_idx_auto<<<(N_EDGES + 255) / 256, 256>>>(ei_raw);
    // launch 1: all-layer W split + zero g_H0 + reset tile counters
    prep_w_all<<<5 * 256, 256>>>((const float*)d_in[4], (const float*)d_in[8],
                                 (const float*)d_in[12], (const float*)d_in[16],
                                 (const float*)d_in[20]);

    // layer l: in_sel / out_sel / zero_sel (1=H0, 2=H1, 3=d_out, 0=none)
    const int in_sel[5]   = {0, 1, 2, 1, 2};
    const int out_sel[5]  = {1, 2, 1, 2, 3};
    const int zero_sel[5] = {2, 1, 2, 3, 0};

    for (int l = 0; l < 5; l++) {
        const float* W1 = (const float*)d_in[2 + 4 * l];
        const float* b1 = (const float*)d_in[3 + 4 * l];
        const float* b2 = (const float*)d_in[5 + 4 * l];

        if (l == 0)
            node_gemm<IN_DIM><<<dim3(63, 2), 256>>>(x, W1, b1, 0);
        else
            node_gemm<HIDDEN><<<dim3(63, 2), 256>>>(x, W1, b1, in_sel[l]);

        // persistent grid: 2 CTAs per SM (152 SMs on GB300)
        edge_hmma_kernel<<<304, 256, SM_TOTAL>>>(
            b2, (float*)d_out, out_sel[l], zero_sel[l], l * HIDDEN * HIDDEN, l);
    }
}